// round 13
// baseline (speedup 1.0000x reference)
#include <cuda_runtime.h>
#include <cuda_fp16.h>
#include <cuda_bf16.h>
#include <math.h>
#include <stdint.h>

#define B_  16
#define L_  1024
#define H_  512
#define KK_ 32
#define BL_ (B_ * L_)          // 16384
#define INVSQ 0.04419417382415922f

// ---------------- scratch (no allocations allowed) ----------------
__device__ float  g_q[B_ * H_];
__device__ float  g_p[B_ * H_];            // Wk^T q (pre-scaled)
__device__ float  g_qbk[B_];               // q . bk (pre-scaled)
__device__ float  g_s[B_ * L_];
__device__ __nv_bfloat16 g_vd[BL_ * H_];   // VD = item @ (Wd Wv)^T, bf16 (gather traffic halved)
__device__ __half g_itemh[BL_ * H_];       // fp16 item (GEMM A)
__device__ __half g_wdh[H_ * H_];          // fp16 Wd
__device__ __half g_wvth[H_ * H_];         // fp16 Wv^T
__device__ __half g_wvdh[H_ * H_];         // fp16 Wvd = Wd @ Wv
__device__ float  g_bvd[H_];               // Wd bv + bd
__device__ float  g_zb[H_];                // zero bias (stays 0)
__device__ int    g_index[L_ * KK_];

__device__ __forceinline__ void cp16(uint32_t d, const void* g) {
    asm volatile("cp.async.cg.shared.global [%0], [%1], 16;" :: "r"(d), "l"(g));
}
__device__ __forceinline__ uint32_t smem_u32(const void* p) {
    uint32_t a;
    asm("{ .reg .u64 t; cvta.to.shared.u64 t, %1; cvt.u32.u64 %0, t; }" : "=r"(a) : "l"(p));
    return a;
}
__device__ __forceinline__ void mma_f16(float* d, const uint32_t* a, const uint32_t* b) {
    asm volatile(
        "mma.sync.aligned.m16n8k16.row.col.f32.f16.f16.f32 "
        "{%0,%1,%2,%3}, {%4,%5,%6,%7}, {%8,%9}, {%0,%1,%2,%3};"
        : "+f"(d[0]), "+f"(d[1]), "+f"(d[2]), "+f"(d[3])
        : "r"(a[0]), "r"(a[1]), "r"(a[2]), "r"(a[3]), "r"(b[0]), "r"(b[1]));
}
__device__ __forceinline__ void ldsm4(uint32_t& r0, uint32_t& r1, uint32_t& r2,
                                      uint32_t& r3, uint32_t addr) {
    asm volatile("ldmatrix.sync.aligned.m8n8.x4.shared.b16 {%0,%1,%2,%3}, [%4];"
        : "=r"(r0), "=r"(r1), "=r"(r2), "=r"(r3) : "r"(addr));
}

// ================ (1) fused prep ================
#define PB_CVT  128
#define PB_ITEM 8192
#define PB_CNV  256
#define PB_BVD  64
#define PREP_BLOCKS (PB_CVT + PB_ITEM + PB_CNV + PB_BVD)

__global__ __launch_bounds__(256) void prep_kernel(
    const void* __restrict__ idx, const float* __restrict__ item,
    const float* __restrict__ Wd, const float* __restrict__ Wv,
    const float* __restrict__ bv, const float* __restrict__ bd)
{
    __shared__ float t[32][33];
    const int bid = blockIdx.x;
    const int tid = threadIdx.x;

    if (bid < PB_CVT) {
        const unsigned int* w = (const unsigned int*)idx;
        unsigned int any = 0;
        #pragma unroll
        for (int i = tid; i < 1024; i += 256) any |= w[2 * i + 1];
        int is64 = (__syncthreads_or((int)any) == 0);
        int i = bid * 256 + tid;
        g_index[i] = is64 ? (int)((const long long*)idx)[i]
                          : ((const int*)idx)[i];
    } else if (bid < PB_CVT + PB_ITEM) {
        int i = (bid - PB_CVT) * 256 + tid;
        float4 v = reinterpret_cast<const float4*>(item)[i];
        uint2 o;
        *reinterpret_cast<__half2*>(&o.x) = __floats2half2_rn(v.x, v.y);
        *reinterpret_cast<__half2*>(&o.y) = __floats2half2_rn(v.z, v.w);
        reinterpret_cast<uint2*>(g_itemh)[i] = o;
    } else if (bid < PB_CVT + PB_ITEM + PB_CNV) {
        int b2 = bid - (PB_CVT + PB_ITEM);
        const int bx = (b2 & 15) * 32, by = (b2 >> 4) * 32;
        const int tx = tid & 31, ty = tid >> 5;
        #pragma unroll
        for (int r = 0; r < 32; r += 8) {
            int row = by + ty + r;
            g_wdh[(size_t)row * H_ + bx + tx] =
                __float2half_rn(Wd[(size_t)row * H_ + bx + tx]);
            t[ty + r][tx] = Wv[(size_t)row * H_ + bx + tx];
        }
        __syncthreads();
        #pragma unroll
        for (int r = 0; r < 32; r += 8) {
            int row = bx + ty + r;
            g_wvth[(size_t)row * H_ + by + tx] = __float2half_rn(t[tx][ty + r]);
        }
    } else {
        int b2 = bid - (PB_CVT + PB_ITEM + PB_CNV);
        int row  = (b2 * 256 + tid) >> 5;
        int lane = tid & 31;
        const float4* w4 = reinterpret_cast<const float4*>(Wd + (size_t)row * H_);
        const float4* b4 = reinterpret_cast<const float4*>(bv);
        float acc = 0.f;
        #pragma unroll
        for (int i = lane; i < H_ / 4; i += 32) {
            float4 w = w4[i], b = b4[i];
            acc += w.x * b.x + w.y * b.y + w.z * b.z + w.w * b.w;
        }
        #pragma unroll
        for (int off = 16; off; off >>= 1)
            acc += __shfl_xor_sync(0xFFFFFFFFu, acc, off);
        if (lane == 0) g_bvd[row] = acc + bd[row];
    }
}

// ---------------- (2) q projection ----------------
__global__ __launch_bounds__(256) void qproj_kernel(
    const float* __restrict__ user, const float* __restrict__ Wq,
    const float* __restrict__ bq)
{
    int o    = (blockIdx.x * blockDim.x + threadIdx.x) >> 5;
    int lane = threadIdx.x & 31;
    int b = o >> 9;
    int n = o & 511;
    const float4* u4 = reinterpret_cast<const float4*>(user + (size_t)b * H_);
    const float4* w4 = reinterpret_cast<const float4*>(Wq + (size_t)n * H_);
    float acc = 0.f;
    #pragma unroll
    for (int i = lane; i < H_ / 4; i += 32) {
        float4 a = u4[i], w = w4[i];
        acc += a.x * w.x + a.y * w.y + a.z * w.z + a.w * w.w;
    }
    #pragma unroll
    for (int off = 16; off; off >>= 1)
        acc += __shfl_xor_sync(0xFFFFFFFFu, acc, off);
    if (lane == 0) g_q[o] = acc + bq[n];
}

// ---------------- (3) p[b] = Wk^T q[b], qbk[b] = q.bk ----------------
__global__ __launch_bounds__(128) void pk_kernel(
    const float* __restrict__ Wk, const float* __restrict__ bk)
{
    const int b  = blockIdx.y;
    const int j  = blockIdx.x * 128 + threadIdx.x;
    const int tid = threadIdx.x;
    __shared__ float qs[H_];
    __shared__ float red[128];
    for (int i = tid; i < H_; i += 128) qs[i] = g_q[b * H_ + i];
    __syncthreads();

    float acc = 0.f;
    #pragma unroll 8
    for (int i = 0; i < H_; i++)
        acc += Wk[(size_t)i * H_ + j] * qs[i];
    g_p[b * H_ + j] = acc * INVSQ;

    if (blockIdx.x == 0) {
        float a = 0.f;
        for (int i = tid; i < H_; i += 128) a += qs[i] * bk[i];
        red[tid] = a;
        __syncthreads();
        #pragma unroll
        for (int s = 64; s; s >>= 1) {
            if (tid < s) red[tid] += red[tid + s];
            __syncthreads();
        }
        if (tid == 0) g_qbk[b] = red[0] * INVSQ;
    }
}

// ---------------- (4) scores ----------------
__global__ __launch_bounds__(256) void score_kernel() {
    int w    = (blockIdx.x * blockDim.x + threadIdx.x) >> 5;
    int lane = threadIdx.x & 31;
    int b = w >> 10;
    const uint2*  ir = reinterpret_cast<const uint2*>(g_itemh + (size_t)w * H_);
    const float4* pr = reinterpret_cast<const float4*>(g_p + (size_t)b * H_);
    float acc = 0.f;
    #pragma unroll
    for (int i = lane; i < H_ / 4; i += 32) {
        uint2 u = ir[i];
        float2 f0 = __half22float2(*reinterpret_cast<__half2*>(&u.x));
        float2 f1 = __half22float2(*reinterpret_cast<__half2*>(&u.y));
        float4 p = pr[i];
        acc += f0.x * p.x + f0.y * p.y + f1.x * p.z + f1.y * p.w;
    }
    #pragma unroll
    for (int off = 16; off; off >>= 1)
        acc += __shfl_xor_sync(0xFFFFFFFFu, acc, off);
    if (lane == 0) g_s[w] = acc + g_qbk[b];
}

// ================= fp16 mma.sync GEMM with ldmatrix ============
// C = A @ W^T (+bias). obf=0: fp16 out (Ch). obf=1: bf16 out (Cb).
#define GH_STRIDE 40
#define GH_TILE   (128 * GH_STRIDE)
#define GH_SLOT   (2 * GH_TILE)
#define GH_SMEM   (3 * GH_SLOT * 2)            // 61440 bytes

__global__ void __launch_bounds__(128) gemm_h_kernel(
    const __half* __restrict__ A, const __half* __restrict__ W,
    const float* __restrict__ bias, __half* __restrict__ Ch,
    __nv_bfloat16* __restrict__ Cb, int obf)
{
    extern __shared__ __half smh[];

    const int tid  = threadIdx.x;
    const int lane = tid & 31;
    const int warp = tid >> 5;
    const int wm   = (warp & 1) * 64;
    const int wn   = (warp >> 1) * 64;
    const int g    = lane >> 2;
    const int t    = lane & 3;
    const int bm   = blockIdx.y * 128;
    const int bn   = blockIdx.x * 128;

    const int lrow = tid >> 2;
    const int lc   = tid & 3;

    const int grp = lane >> 3, lr = lane & 7;
    const uint32_t aoff = (uint32_t)((wm + (grp & 1) * 8 + lr) * 80 + (grp >> 1) * 16);
    const uint32_t boff = (uint32_t)((wn + (grp >> 1) * 8 + lr) * 80 + (grp & 1) * 16);

    const __half* Abase = A + (size_t)bm * H_ + lc * 8;
    const __half* Bbase = W + (size_t)bn * H_ + lc * 8;

    float acc[4][8][4];
    #pragma unroll
    for (int mi = 0; mi < 4; mi++)
        #pragma unroll
        for (int ni = 0; ni < 8; ni++)
            #pragma unroll
            for (int r = 0; r < 4; r++) acc[mi][ni][r] = 0.f;

    const uint32_t smb = smem_u32(smh);
    const int NST = H_ / 32;   // 16

    #pragma unroll
    for (int p = 0; p < 2; p++) {
        const uint32_t ab = smb + (uint32_t)(p * GH_SLOT) * 2;
        const uint32_t bb = ab + GH_TILE * 2;
        const int k0 = p * 32;
        #pragma unroll
        for (int i = 0; i < 4; i++) {
            int row = lrow + i * 32;
            uint32_t off = (uint32_t)(row * 80 + lc * 16);
            cp16(ab + off, Abase + (size_t)row * H_ + k0);
            cp16(bb + off, Bbase + (size_t)row * H_ + k0);
        }
        asm volatile("cp.async.commit_group;" ::: "memory");
    }

    for (int s = 0; s < NST; s++) {
        if (s < NST - 1) asm volatile("cp.async.wait_group 1;" ::: "memory");
        else             asm volatile("cp.async.wait_group 0;" ::: "memory");
        __syncthreads();

        if (s + 2 < NST) {
            const int slot = (s + 2) % 3;
            const uint32_t ab = smb + (uint32_t)(slot * GH_SLOT) * 2;
            const uint32_t bb = ab + GH_TILE * 2;
            const int k0 = (s + 2) * 32;
            #pragma unroll
            for (int i = 0; i < 4; i++) {
                int row = lrow + i * 32;
                uint32_t off = (uint32_t)(row * 80 + lc * 16);
                cp16(ab + off, Abase + (size_t)row * H_ + k0);
                cp16(bb + off, Bbase + (size_t)row * H_ + k0);
            }
            asm volatile("cp.async.commit_group;" ::: "memory");
        }

        const uint32_t aA = smb + (uint32_t)((s % 3) * GH_SLOT) * 2 + aoff;
        const uint32_t aB = smb + (uint32_t)((s % 3) * GH_SLOT) * 2 + GH_TILE * 2 + boff;
        #pragma unroll
        for (int kk = 0; kk < 2; kk++) {
            uint32_t af[4][4], bf[8][2];
            #pragma unroll
            for (int mi = 0; mi < 4; mi++)
                ldsm4(af[mi][0], af[mi][1], af[mi][2], af[mi][3],
                      aA + (uint32_t)(mi * 1280 + kk * 32));
            #pragma unroll
            for (int nj = 0; nj < 4; nj++)
                ldsm4(bf[2 * nj][0], bf[2 * nj][1], bf[2 * nj + 1][0], bf[2 * nj + 1][1],
                      aB + (uint32_t)(nj * 1280 + kk * 32));
            #pragma unroll
            for (int mi = 0; mi < 4; mi++)
                #pragma unroll
                for (int ni = 0; ni < 8; ni++)
                    mma_f16(acc[mi][ni], af[mi], bf[ni]);
        }
    }

    // ---- epilogue ----
    #pragma unroll
    for (int mi = 0; mi < 4; mi++) {
        const int m0 = bm + wm + mi * 16 + g;
        #pragma unroll
        for (int ni = 0; ni < 8; ni++) {
            const int n = bn + wn + ni * 8 + 2 * t;
            float2 bs = *reinterpret_cast<const float2*>(bias + n);
            float o0x = acc[mi][ni][0] + bs.x, o0y = acc[mi][ni][1] + bs.y;
            float o1x = acc[mi][ni][2] + bs.x, o1y = acc[mi][ni][3] + bs.y;
            if (obf) {
                *reinterpret_cast<__nv_bfloat162*>(Cb + (size_t)m0 * H_ + n) =
                    __floats2bfloat162_rn(o0x, o0y);
                *reinterpret_cast<__nv_bfloat162*>(Cb + (size_t)(m0 + 8) * H_ + n) =
                    __floats2bfloat162_rn(o1x, o1y);
            } else {
                *reinterpret_cast<__half2*>(Ch + (size_t)m0 * H_ + n) =
                    __floats2half2_rn(o0x, o0y);
                *reinterpret_cast<__half2*>(Ch + (size_t)(m0 + 8) * H_ + n) =
                    __floats2half2_rn(o1x, o1y);
            }
        }
    }
}

// ------- fused: gather + softmax + weighted bf16-VD sum + bvd + residual + LN ----
__global__ __launch_bounds__(128) void attn_ln_kernel(
    const float* __restrict__ mask, const float* __restrict__ item,
    const float* __restrict__ gma, const float* __restrict__ bta,
    float* __restrict__ out)
{
    __shared__ float wsh[KK_];
    __shared__ int   ish[KK_];
    __shared__ float sh[8];
    const int bl  = blockIdx.x;
    const int b   = bl >> 10;
    const int l   = bl & 1023;
    const int tid = threadIdx.x;

    if (tid < KK_) {
        int   idx = g_index[l * KK_ + tid];
        float s   = g_s[b * L_ + idx] + mask[(size_t)bl * KK_ + tid];
        ish[tid]  = idx;
        float mx = s;
        #pragma unroll
        for (int o = 16; o; o >>= 1)
            mx = fmaxf(mx, __shfl_xor_sync(0xFFFFFFFFu, mx, o));
        float e = expf(s - mx);
        float sum = e;
        #pragma unroll
        for (int o = 16; o; o >>= 1)
            sum += __shfl_xor_sync(0xFFFFFFFFu, sum, o);
        wsh[tid] = e / sum;
    }
    __syncthreads();

    // each thread: 4 consecutive h (one uint2 = 4 bf16)
    const uint2* vd = reinterpret_cast<const uint2*>(g_vd);
    float4 acc = make_float4(0.f, 0.f, 0.f, 0.f);
    #pragma unroll 8
    for (int k = 0; k < KK_; k++) {
        float wk = wsh[k];
        uint2 u  = vd[((size_t)(b * L_ + ish[k])) * (H_ / 4) + tid];
        float2 f0 = __bfloat1622float2(*reinterpret_cast<__nv_bfloat162*>(&u.x));
        float2 f1 = __bfloat1622float2(*reinterpret_cast<__nv_bfloat162*>(&u.y));
        acc.x += wk * f0.x;
        acc.y += wk * f0.y;
        acc.z += wk * f1.x;
        acc.w += wk * f1.y;
    }
    float4 it = reinterpret_cast<const float4*>(item)[(size_t)bl * (H_ / 4) + tid];
    float4 bv = reinterpret_cast<const float4*>(g_bvd)[tid];
    float4 v;
    v.x = acc.x + bv.x + it.x;
    v.y = acc.y + bv.y + it.y;
    v.z = acc.z + bv.z + it.z;
    v.w = acc.w + bv.w + it.w;

    float s  = v.x + v.y + v.z + v.w;
    float ss = v.x * v.x + v.y * v.y + v.z * v.z + v.w * v.w;
    #pragma unroll
    for (int o = 16; o; o >>= 1) {
        s  += __shfl_xor_sync(0xFFFFFFFFu, s, o);
        ss += __shfl_xor_sync(0xFFFFFFFFu, ss, o);
    }
    int wid = tid >> 5, lane = tid & 31;
    if (lane == 0) { sh[wid] = s; sh[4 + wid] = ss; }
    __syncthreads();
    if (tid == 0) {
        float S  = sh[0] + sh[1] + sh[2] + sh[3];
        float SS = sh[4] + sh[5] + sh[6] + sh[7];
        sh[0] = S; sh[1] = SS;
    }
    __syncthreads();
    float mu  = sh[0] * (1.f / 512.f);
    float var = sh[1] * (1.f / 512.f) - mu * mu;
    float inv = rsqrtf(var + 1e-12f);

    float4 g4 = reinterpret_cast<const float4*>(gma)[tid];
    float4 b4 = reinterpret_cast<const float4*>(bta)[tid];
    float4 o;
    o.x = (v.x - mu) * inv * g4.x + b4.x;
    o.y = (v.y - mu) * inv * g4.y + b4.y;
    o.z = (v.z - mu) * inv * g4.z + b4.z;
    o.w = (v.w - mu) * inv * g4.w + b4.w;
    reinterpret_cast<float4*>(out)[(size_t)bl * (H_ / 4) + tid] = o;
}

// ---------------- launch ----------------
extern "C" void kernel_launch(void* const* d_in, const int* in_sizes, int n_in,
                              void* d_out, int out_size)
{
    const float* user  = (const float*)d_in[0];
    const float* item  = (const float*)d_in[1];
    const float* mask  = (const float*)d_in[2];
    const void*  indexp =               d_in[3];
    const float* Wq    = (const float*)d_in[4];
    const float* bq    = (const float*)d_in[5];
    const float* Wk    = (const float*)d_in[6];
    const float* bk    = (const float*)d_in[7];
    const float* Wv    = (const float*)d_in[8];
    const float* bv    = (const float*)d_in[9];
    const float* Wd    = (const float*)d_in[10];
    const float* bd    = (const float*)d_in[11];
    const float* lng   = (const float*)d_in[12];
    const float* lnb   = (const float*)d_in[13];
    float* out = (float*)d_out;

    __half *itemhp, *wdhp, *wvthp, *wvdhp;
    __nv_bfloat16 *vdp;
    float *zbp;
    cudaGetSymbolAddress((void**)&vdp,    g_vd);
    cudaGetSymbolAddress((void**)&itemhp, g_itemh);
    cudaGetSymbolAddress((void**)&wdhp,   g_wdh);
    cudaGetSymbolAddress((void**)&wvthp,  g_wvth);
    cudaGetSymbolAddress((void**)&wvdhp,  g_wvdh);
    cudaGetSymbolAddress((void**)&zbp,    g_zb);

    cudaFuncSetAttribute(gemm_h_kernel, cudaFuncAttributeMaxDynamicSharedMemorySize, GH_SMEM);

    // (1) fused prep
    prep_kernel<<<PREP_BLOCKS, 256>>>(indexp, item, Wd, Wv, bv, bd);

    // (2) q projection, (3) p = Wk^T q
    qproj_kernel<<<(B_ * H_) / 8, 256>>>(user, Wq, bq);
    pk_kernel<<<dim3(H_ / 128, B_), 128>>>(Wk, bk);

    // (4) scores
    score_kernel<<<BL_ / 8, 256>>>();

    // (5) Wvd = Wd @ Wv (fp16 out)
    gemm_h_kernel<<<dim3(4, 4), 128, GH_SMEM>>>(wdhp, wvthp, zbp, wvdhp, nullptr, 0);

    // (6) VD = item_h @ Wvd^T (bf16 out)
    gemm_h_kernel<<<dim3(H_ / 128, BL_ / 128), 128, GH_SMEM>>>(itemhp, wvdhp, zbp, nullptr, vdp, 1);

    // (7) fused gather + softmax + bvd + residual + LN -> out
    attn_ln_kernel<<<BL_, 128>>>(mask, item, lng, lnb, out);
}

// round 14
// speedup vs baseline: 1.0331x; 1.0331x over previous
#include <cuda_runtime.h>
#include <cuda_fp16.h>
#include <math.h>
#include <stdint.h>

#define B_  16
#define L_  1024
#define H_  512
#define KK_ 32
#define BL_ (B_ * L_)          // 16384
#define INVSQ 0.04419417382415922f

// ---------------- scratch (no allocations allowed) ----------------
__device__ float  g_q[B_ * H_];
__device__ float  g_p[B_ * H_];            // Wk^T q (pre-scaled)
__device__ float  g_qbk[B_];               // q . bk (pre-scaled)
__device__ float  g_s[B_ * L_];
__device__ __half g_vd[BL_ * H_];          // VD = item @ (Wd Wv)^T, fp16
__device__ __half g_itemh[BL_ * H_];       // fp16 item (GEMM A)
__device__ __half g_wdh[H_ * H_];          // fp16 Wd
__device__ __half g_wvth[H_ * H_];         // fp16 Wv^T
__device__ __half g_wvdh[H_ * H_];         // fp16 Wvd = Wd @ Wv
__device__ float  g_bvd[H_];               // Wd bv + bd
__device__ float  g_zb[H_];                // zero bias (stays 0)
__device__ int    g_index[L_ * KK_];

__device__ __forceinline__ void cp16(uint32_t d, const void* g) {
    asm volatile("cp.async.cg.shared.global [%0], [%1], 16;" :: "r"(d), "l"(g));
}
__device__ __forceinline__ uint32_t smem_u32(const void* p) {
    uint32_t a;
    asm("{ .reg .u64 t; cvta.to.shared.u64 t, %1; cvt.u32.u64 %0, t; }" : "=r"(a) : "l"(p));
    return a;
}
__device__ __forceinline__ void mma_f16(float* d, const uint32_t* a, const uint32_t* b) {
    asm volatile(
        "mma.sync.aligned.m16n8k16.row.col.f32.f16.f16.f32 "
        "{%0,%1,%2,%3}, {%4,%5,%6,%7}, {%8,%9}, {%0,%1,%2,%3};"
        : "+f"(d[0]), "+f"(d[1]), "+f"(d[2]), "+f"(d[3])
        : "r"(a[0]), "r"(a[1]), "r"(a[2]), "r"(a[3]), "r"(b[0]), "r"(b[1]));
}
__device__ __forceinline__ void ldsm4(uint32_t& r0, uint32_t& r1, uint32_t& r2,
                                      uint32_t& r3, uint32_t addr) {
    asm volatile("ldmatrix.sync.aligned.m8n8.x4.shared.b16 {%0,%1,%2,%3}, [%4];"
        : "=r"(r0), "=r"(r1), "=r"(r2), "=r"(r3) : "r"(addr));
}

// ================ (1) fused prep ================
#define PB_CVT  128
#define PB_ITEM 8192
#define PB_CNV  256
#define PB_BVD  64
#define PREP_BLOCKS (PB_CVT + PB_ITEM + PB_CNV + PB_BVD)

__global__ __launch_bounds__(256) void prep_kernel(
    const void* __restrict__ idx, const float* __restrict__ item,
    const float* __restrict__ Wd, const float* __restrict__ Wv,
    const float* __restrict__ bv, const float* __restrict__ bd)
{
    __shared__ float t[32][33];
    const int bid = blockIdx.x;
    const int tid = threadIdx.x;

    if (bid < PB_CVT) {
        const unsigned int* w = (const unsigned int*)idx;
        unsigned int any = 0;
        #pragma unroll
        for (int i = tid; i < 1024; i += 256) any |= w[2 * i + 1];
        int is64 = (__syncthreads_or((int)any) == 0);
        int i = bid * 256 + tid;
        g_index[i] = is64 ? (int)((const long long*)idx)[i]
                          : ((const int*)idx)[i];
    } else if (bid < PB_CVT + PB_ITEM) {
        int i = (bid - PB_CVT) * 256 + tid;
        float4 v = reinterpret_cast<const float4*>(item)[i];
        uint2 o;
        *reinterpret_cast<__half2*>(&o.x) = __floats2half2_rn(v.x, v.y);
        *reinterpret_cast<__half2*>(&o.y) = __floats2half2_rn(v.z, v.w);
        reinterpret_cast<uint2*>(g_itemh)[i] = o;
    } else if (bid < PB_CVT + PB_ITEM + PB_CNV) {
        int b2 = bid - (PB_CVT + PB_ITEM);
        const int bx = (b2 & 15) * 32, by = (b2 >> 4) * 32;
        const int tx = tid & 31, ty = tid >> 5;
        #pragma unroll
        for (int r = 0; r < 32; r += 8) {
            int row = by + ty + r;
            g_wdh[(size_t)row * H_ + bx + tx] =
                __float2half_rn(Wd[(size_t)row * H_ + bx + tx]);
            t[ty + r][tx] = Wv[(size_t)row * H_ + bx + tx];
        }
        __syncthreads();
        #pragma unroll
        for (int r = 0; r < 32; r += 8) {
            int row = bx + ty + r;
            g_wvth[(size_t)row * H_ + by + tx] = __float2half_rn(t[tx][ty + r]);
        }
    } else {
        int b2 = bid - (PB_CVT + PB_ITEM + PB_CNV);
        int row  = (b2 * 256 + tid) >> 5;
        int lane = tid & 31;
        const float4* w4 = reinterpret_cast<const float4*>(Wd + (size_t)row * H_);
        const float4* b4 = reinterpret_cast<const float4*>(bv);
        float acc = 0.f;
        #pragma unroll
        for (int i = lane; i < H_ / 4; i += 32) {
            float4 w = w4[i], b = b4[i];
            acc += w.x * b.x + w.y * b.y + w.z * b.z + w.w * b.w;
        }
        #pragma unroll
        for (int off = 16; off; off >>= 1)
            acc += __shfl_xor_sync(0xFFFFFFFFu, acc, off);
        if (lane == 0) g_bvd[row] = acc + bd[row];
    }
}

// ---------------- q projection ----------------
__global__ __launch_bounds__(256) void qproj_kernel(
    const float* __restrict__ user, const float* __restrict__ Wq,
    const float* __restrict__ bq)
{
    int o    = (blockIdx.x * blockDim.x + threadIdx.x) >> 5;
    int lane = threadIdx.x & 31;
    int b = o >> 9;
    int n = o & 511;
    const float4* u4 = reinterpret_cast<const float4*>(user + (size_t)b * H_);
    const float4* w4 = reinterpret_cast<const float4*>(Wq + (size_t)n * H_);
    float acc = 0.f;
    #pragma unroll
    for (int i = lane; i < H_ / 4; i += 32) {
        float4 a = u4[i], w = w4[i];
        acc += a.x * w.x + a.y * w.y + a.z * w.z + a.w * w.w;
    }
    #pragma unroll
    for (int off = 16; off; off >>= 1)
        acc += __shfl_xor_sync(0xFFFFFFFFu, acc, off);
    if (lane == 0) g_q[o] = acc + bq[n];
}

// ---------------- p[b] = Wk^T q[b], qbk[b] = q.bk ----------------
__global__ __launch_bounds__(128) void pk_kernel(
    const float* __restrict__ Wk, const float* __restrict__ bk)
{
    const int b  = blockIdx.y;
    const int j  = blockIdx.x * 128 + threadIdx.x;
    const int tid = threadIdx.x;
    __shared__ float qs[H_];
    __shared__ float red[128];
    for (int i = tid; i < H_; i += 128) qs[i] = g_q[b * H_ + i];
    __syncthreads();

    float acc = 0.f;
    #pragma unroll 8
    for (int i = 0; i < H_; i++)
        acc += Wk[(size_t)i * H_ + j] * qs[i];
    g_p[b * H_ + j] = acc * INVSQ;

    if (blockIdx.x == 0) {
        float a = 0.f;
        for (int i = tid; i < H_; i += 128) a += qs[i] * bk[i];
        red[tid] = a;
        __syncthreads();
        #pragma unroll
        for (int s = 64; s; s >>= 1) {
            if (tid < s) red[tid] += red[tid + s];
            __syncthreads();
        }
        if (tid == 0) g_qbk[b] = red[0] * INVSQ;
    }
}

// ---------------- scores ----------------
__global__ __launch_bounds__(256) void score_kernel() {
    int w    = (blockIdx.x * blockDim.x + threadIdx.x) >> 5;
    int lane = threadIdx.x & 31;
    int b = w >> 10;
    const uint2*  ir = reinterpret_cast<const uint2*>(g_itemh + (size_t)w * H_);
    const float4* pr = reinterpret_cast<const float4*>(g_p + (size_t)b * H_);
    float acc = 0.f;
    #pragma unroll
    for (int i = lane; i < H_ / 4; i += 32) {
        uint2 u = ir[i];
        float2 f0 = __half22float2(*reinterpret_cast<__half2*>(&u.x));
        float2 f1 = __half22float2(*reinterpret_cast<__half2*>(&u.y));
        float4 p = pr[i];
        acc += f0.x * p.x + f0.y * p.y + f1.x * p.z + f1.y * p.w;
    }
    #pragma unroll
    for (int off = 16; off; off >>= 1)
        acc += __shfl_xor_sync(0xFFFFFFFFu, acc, off);
    if (lane == 0) g_s[w] = acc + g_qbk[b];
}

// ================= fp16 mma.sync GEMM with ldmatrix ============
#define GH_STRIDE 40
#define GH_TILE   (128 * GH_STRIDE)
#define GH_SLOT   (2 * GH_TILE)
#define GH_SMEM   (3 * GH_SLOT * 2)            // 61440 bytes

__global__ void __launch_bounds__(128) gemm_h_kernel(
    const __half* __restrict__ A, const __half* __restrict__ W,
    const float* __restrict__ bias, __half* __restrict__ Ch)
{
    extern __shared__ __half smh[];

    const int tid  = threadIdx.x;
    const int lane = tid & 31;
    const int warp = tid >> 5;
    const int wm   = (warp & 1) * 64;
    const int wn   = (warp >> 1) * 64;
    const int g    = lane >> 2;
    const int t    = lane & 3;
    const int bm   = blockIdx.y * 128;
    const int bn   = blockIdx.x * 128;

    const int lrow = tid >> 2;
    const int lc   = tid & 3;

    const int grp = lane >> 3, lr = lane & 7;
    const uint32_t aoff = (uint32_t)((wm + (grp & 1) * 8 + lr) * 80 + (grp >> 1) * 16);
    const uint32_t boff = (uint32_t)((wn + (grp >> 1) * 8 + lr) * 80 + (grp & 1) * 16);

    const __half* Abase = A + (size_t)bm * H_ + lc * 8;
    const __half* Bbase = W + (size_t)bn * H_ + lc * 8;

    float acc[4][8][4];
    #pragma unroll
    for (int mi = 0; mi < 4; mi++)
        #pragma unroll
        for (int ni = 0; ni < 8; ni++)
            #pragma unroll
            for (int r = 0; r < 4; r++) acc[mi][ni][r] = 0.f;

    const uint32_t smb = smem_u32(smh);
    const int NST = H_ / 32;   // 16

    #pragma unroll
    for (int p = 0; p < 2; p++) {
        const uint32_t ab = smb + (uint32_t)(p * GH_SLOT) * 2;
        const uint32_t bb = ab + GH_TILE * 2;
        const int k0 = p * 32;
        #pragma unroll
        for (int i = 0; i < 4; i++) {
            int row = lrow + i * 32;
            uint32_t off = (uint32_t)(row * 80 + lc * 16);
            cp16(ab + off, Abase + (size_t)row * H_ + k0);
            cp16(bb + off, Bbase + (size_t)row * H_ + k0);
        }
        asm volatile("cp.async.commit_group;" ::: "memory");
    }

    for (int s = 0; s < NST; s++) {
        if (s < NST - 1) asm volatile("cp.async.wait_group 1;" ::: "memory");
        else             asm volatile("cp.async.wait_group 0;" ::: "memory");
        __syncthreads();

        if (s + 2 < NST) {
            const int slot = (s + 2) % 3;
            const uint32_t ab = smb + (uint32_t)(slot * GH_SLOT) * 2;
            const uint32_t bb = ab + GH_TILE * 2;
            const int k0 = (s + 2) * 32;
            #pragma unroll
            for (int i = 0; i < 4; i++) {
                int row = lrow + i * 32;
                uint32_t off = (uint32_t)(row * 80 + lc * 16);
                cp16(ab + off, Abase + (size_t)row * H_ + k0);
                cp16(bb + off, Bbase + (size_t)row * H_ + k0);
            }
            asm volatile("cp.async.commit_group;" ::: "memory");
        }

        const uint32_t aA = smb + (uint32_t)((s % 3) * GH_SLOT) * 2 + aoff;
        const uint32_t aB = smb + (uint32_t)((s % 3) * GH_SLOT) * 2 + GH_TILE * 2 + boff;
        #pragma unroll
        for (int kk = 0; kk < 2; kk++) {
            uint32_t af[4][4], bf[8][2];
            #pragma unroll
            for (int mi = 0; mi < 4; mi++)
                ldsm4(af[mi][0], af[mi][1], af[mi][2], af[mi][3],
                      aA + (uint32_t)(mi * 1280 + kk * 32));
            #pragma unroll
            for (int nj = 0; nj < 4; nj++)
                ldsm4(bf[2 * nj][0], bf[2 * nj][1], bf[2 * nj + 1][0], bf[2 * nj + 1][1],
                      aB + (uint32_t)(nj * 1280 + kk * 32));
            #pragma unroll
            for (int mi = 0; mi < 4; mi++)
                #pragma unroll
                for (int ni = 0; ni < 8; ni++)
                    mma_f16(acc[mi][ni], af[mi], bf[ni]);
        }
    }

    // ---- epilogue: fp16 out (+bias) ----
    #pragma unroll
    for (int mi = 0; mi < 4; mi++) {
        const int m0 = bm + wm + mi * 16 + g;
        #pragma unroll
        for (int ni = 0; ni < 8; ni++) {
            const int n = bn + wn + ni * 8 + 2 * t;
            float2 bs = *reinterpret_cast<const float2*>(bias + n);
            *reinterpret_cast<__half2*>(Ch + (size_t)m0 * H_ + n) =
                __floats2half2_rn(acc[mi][ni][0] + bs.x, acc[mi][ni][1] + bs.y);
            *reinterpret_cast<__half2*>(Ch + (size_t)(m0 + 8) * H_ + n) =
                __floats2half2_rn(acc[mi][ni][2] + bs.x, acc[mi][ni][3] + bs.y);
        }
    }
}

// ------- fused: gather + softmax + weighted VD sum + bvd + residual + LN ----
__global__ __launch_bounds__(128) void attn_ln_kernel(
    const float* __restrict__ mask, const float* __restrict__ item,
    const float* __restrict__ gma, const float* __restrict__ bta,
    float* __restrict__ out)
{
    __shared__ float wsh[KK_];
    __shared__ int   ish[KK_];
    __shared__ float sh[8];
    const int bl  = blockIdx.x;
    const int b   = bl >> 10;
    const int l   = bl & 1023;
    const int tid = threadIdx.x;

    if (tid < KK_) {
        int   idx = g_index[l * KK_ + tid];
        float s   = g_s[b * L_ + idx] + mask[(size_t)bl * KK_ + tid];
        ish[tid]  = idx;
        float mx = s;
        #pragma unroll
        for (int o = 16; o; o >>= 1)
            mx = fmaxf(mx, __shfl_xor_sync(0xFFFFFFFFu, mx, o));
        float e = expf(s - mx);
        float sum = e;
        #pragma unroll
        for (int o = 16; o; o >>= 1)
            sum += __shfl_xor_sync(0xFFFFFFFFu, sum, o);
        wsh[tid] = e / sum;
    }
    __syncthreads();

    const uint2* vd = reinterpret_cast<const uint2*>(g_vd);
    float4 acc = make_float4(0.f, 0.f, 0.f, 0.f);
    #pragma unroll 16
    for (int k = 0; k < KK_; k++) {
        float wk = wsh[k];
        uint2 u  = vd[((size_t)(b * L_ + ish[k])) * (H_ / 4) + tid];
        float2 f0 = __half22float2(*reinterpret_cast<__half2*>(&u.x));
        float2 f1 = __half22float2(*reinterpret_cast<__half2*>(&u.y));
        acc.x += wk * f0.x;
        acc.y += wk * f0.y;
        acc.z += wk * f1.x;
        acc.w += wk * f1.y;
    }
    float4 it = reinterpret_cast<const float4*>(item)[(size_t)bl * (H_ / 4) + tid];
    float4 bv = reinterpret_cast<const float4*>(g_bvd)[tid];
    float4 v;
    v.x = acc.x + bv.x + it.x;
    v.y = acc.y + bv.y + it.y;
    v.z = acc.z + bv.z + it.z;
    v.w = acc.w + bv.w + it.w;

    float s  = v.x + v.y + v.z + v.w;
    float ss = v.x * v.x + v.y * v.y + v.z * v.z + v.w * v.w;
    #pragma unroll
    for (int o = 16; o; o >>= 1) {
        s  += __shfl_xor_sync(0xFFFFFFFFu, s, o);
        ss += __shfl_xor_sync(0xFFFFFFFFu, ss, o);
    }
    int wid = tid >> 5, lane = tid & 31;
    if (lane == 0) { sh[wid] = s; sh[4 + wid] = ss; }
    __syncthreads();
    if (tid == 0) {
        float S  = sh[0] + sh[1] + sh[2] + sh[3];
        float SS = sh[4] + sh[5] + sh[6] + sh[7];
        sh[0] = S; sh[1] = SS;
    }
    __syncthreads();
    float mu  = sh[0] * (1.f / 512.f);
    float var = sh[1] * (1.f / 512.f) - mu * mu;
    float inv = rsqrtf(var + 1e-12f);

    float4 g4 = reinterpret_cast<const float4*>(gma)[tid];
    float4 b4 = reinterpret_cast<const float4*>(bta)[tid];
    float4 o;
    o.x = (v.x - mu) * inv * g4.x + b4.x;
    o.y = (v.y - mu) * inv * g4.y + b4.y;
    o.z = (v.z - mu) * inv * g4.z + b4.z;
    o.w = (v.w - mu) * inv * g4.w + b4.w;
    reinterpret_cast<float4*>(out)[(size_t)bl * (H_ / 4) + tid] = o;
}

// ---------------- launch ----------------
extern "C" void kernel_launch(void* const* d_in, const int* in_sizes, int n_in,
                              void* d_out, int out_size)
{
    const float* user  = (const float*)d_in[0];
    const float* item  = (const float*)d_in[1];
    const float* mask  = (const float*)d_in[2];
    const void*  indexp =               d_in[3];
    const float* Wq    = (const float*)d_in[4];
    const float* bq    = (const float*)d_in[5];
    const float* Wk    = (const float*)d_in[6];
    const float* bk    = (const float*)d_in[7];
    const float* Wv    = (const float*)d_in[8];
    const float* bv    = (const float*)d_in[9];
    const float* Wd    = (const float*)d_in[10];
    const float* bd    = (const float*)d_in[11];
    const float* lng   = (const float*)d_in[12];
    const float* lnb   = (const float*)d_in[13];
    float* out = (float*)d_out;

    __half *vdp, *itemhp, *wdhp, *wvthp, *wvdhp;
    float *zbp;
    cudaGetSymbolAddress((void**)&vdp,    g_vd);
    cudaGetSymbolAddress((void**)&itemhp, g_itemh);
    cudaGetSymbolAddress((void**)&wdhp,   g_wdh);
    cudaGetSymbolAddress((void**)&wvthp,  g_wvth);
    cudaGetSymbolAddress((void**)&wvdhp,  g_wvdh);
    cudaGetSymbolAddress((void**)&zbp,    g_zb);

    cudaFuncSetAttribute(gemm_h_kernel, cudaFuncAttributeMaxDynamicSharedMemorySize, GH_SMEM);

    // (1) fused prep
    prep_kernel<<<PREP_BLOCKS, 256>>>(indexp, item, Wd, Wv, bv, bd);

    // (2) Wvd = Wd @ Wv (fp16 out)
    gemm_h_kernel<<<dim3(4, 4), 128, GH_SMEM>>>(wdhp, wvthp, zbp, wvdhp);

    // (3) q projection
    qproj_kernel<<<(B_ * H_) / 8, 256>>>(user, Wq, bq);

    // (4) VD = item_h @ Wvd^T  <- lands in the ncu sampling slot
    gemm_h_kernel<<<dim3(H_ / 128, BL_ / 128), 128, GH_SMEM>>>(itemhp, wvdhp, zbp, vdp);

    // (5) p = Wk^T q
    pk_kernel<<<dim3(H_ / 128, B_), 128>>>(Wk, bk);

    // (6) scores
    score_kernel<<<BL_ / 8, 256>>>();

    // (7) fused gather + softmax + bvd + residual + LN -> out
    attn_ln_kernel<<<BL_, 128>>>(mask, item, lng, lnb, out);
}